// round 6
// baseline (speedup 1.0000x reference)
#include <cuda_runtime.h>
#include <math.h>

#define BB 4
#define NN 20000
#define EE 16
#define CC 128
#define BN (BB*NN)

#define THREADS 512
#define NPW 4                  // gather: nodes per warp (16 warps x 4 = 64)
#define GW  8                  // gemv:   nodes per warp (8 groups x 2 k-halves)
#define NPB 64                 // nodes per CTA

typedef unsigned long long u64;

// Scratch (+1 zero pad row at index BN for -1 edges)
__device__ float g_isd[BN];
__device__ float g_bufA[((size_t)BN + 1) * CC];
__device__ float g_bufB[((size_t)BN + 1) * CC];
__device__ float g_Wt[3][CC * CC];   // pre-transposed: Wt[c*128+o] = W[o*128+c]

union F4 { float4 v; u64 p[2]; float f[4]; };

__device__ __forceinline__ u64 fma2(u64 a, u64 b, u64 c) {
    u64 d; asm("fma.rn.f32x2 %0,%1,%2,%3;" : "=l"(d) : "l"(a), "l"(b), "l"(c)); return d;
}
__device__ __forceinline__ u64 add2(u64 a, u64 b) {
    u64 d; asm("add.rn.f32x2 %0,%1,%2;" : "=l"(d) : "l"(a), "l"(b)); return d;
}
__device__ __forceinline__ u64 mul2(u64 a, u64 b) {
    u64 d; asm("mul.rn.f32x2 %0,%1,%2;" : "=l"(d) : "l"(a), "l"(b)); return d;
}
__device__ __forceinline__ u64 dup2(float s) {
    u64 d; asm("mov.b64 %0,{%1,%1};" : "=l"(d) : "f"(s)); return d;
}
__device__ __forceinline__ float elu(float v) { return v > 0.0f ? v : expm1f(v); }

// ---- prep kernels ----
__global__ void isd_kernel(const int* __restrict__ edge) {
    int g = blockIdx.x * blockDim.x + threadIdx.x;
    if (g >= BN) return;
    const int* e = edge + (size_t)g * EE;
    int d = 1;
#pragma unroll
    for (int i = 0; i < EE; i++) d += (e[i] >= 0);
    g_isd[g] = rsqrtf((float)d);
}

// z0 = x * isd -> bufA; zero pad rows of both buffers
__global__ void zprep_kernel(const float* __restrict__ x) {
    int t = blockIdx.x * blockDim.x + threadIdx.x;   // one float4 per thread
    if (t < BN * (CC / 4)) {
        int row = t >> 5;
        float s = g_isd[row];
        F4 v; v.v = *(const float4*)(x + (size_t)t * 4);
        u64 sd = dup2(s);
        v.p[0] = mul2(v.p[0], sd);
        v.p[1] = mul2(v.p[1], sd);
        *(float4*)(g_bufA + (size_t)t * 4) = v.v;
    } else {
        int r = t - BN * (CC / 4);
        if (r < CC / 4) {
            *(float4*)(g_bufA + (size_t)BN * CC + r * 4) = make_float4(0, 0, 0, 0);
            *(float4*)(g_bufB + (size_t)BN * CC + r * 4) = make_float4(0, 0, 0, 0);
        }
    }
}

// Transpose all three W's once: Wt[l][c*128+o] = W_l[o*128+c]
__global__ void wtrans_kernel(const float* __restrict__ W0,
                              const float* __restrict__ W1,
                              const float* __restrict__ W2) {
    int t = blockIdx.x * blockDim.x + threadIdx.x;
    if (t >= 3 * CC * CC) return;
    int l = t / (CC * CC), i = t % (CC * CC);
    int c = i >> 7, o = i & 127;
    const float* W = (l == 0) ? W0 : (l == 1) ? W1 : W2;
    g_Wt[l][i] = W[o * CC + c];
}

// ---- fused layer ----
// u[n]   = isd[n] * ( z[n] + sum_e z[nbr] )       (z pre-scaled by isd)
// v[n]   = u[n] @ W^T                             (K-split over warp pairs)
// out[n] = LAST ? ELU(v) : ELU(v) * isd[n]
template<bool LAST>
__global__ __launch_bounds__(THREADS, 2)
void layer_kernel(const float* __restrict__ zin,
                  const int*   __restrict__ edge,
                  const float* __restrict__ Wt,     // pre-transposed [c][o]
                  float*       __restrict__ out)
{
    __shared__ float us[NPB * CC];    // 32 KB; reused for k-half-1 partials

    const int t = threadIdx.x, w = t >> 5, lane = t & 31;
    const int node0 = blockIdx.x * NPB;

    // ---- Gather: warp handles 4 nodes; lane owns channels [4*lane, 4*lane+4) ----
    {
        F4    acc[NPW];
        int   eidx[NPW];
        float sn[NPW];
#pragma unroll
        for (int i = 0; i < NPW; i++) {
            const int gn = node0 + w * NPW + i;
            sn[i] = g_isd[gn];
            int m = -1;
            if (lane < EE) m = edge[(size_t)gn * EE + lane];
            eidx[i] = (m < 0) ? BN : ((gn / NN) * NN + m);
            acc[i].v = __ldcs((const float4*)(zin + (size_t)gn * CC) + lane);
        }

#pragma unroll 4
        for (int e = 0; e < EE; e++) {
#pragma unroll
            for (int i = 0; i < NPW; i++) {
                int m = __shfl_sync(0xffffffffu, eidx[i], e);
                F4 v; v.v = __ldcs((const float4*)(zin + (size_t)m * CC) + lane);
                acc[i].p[0] = add2(acc[i].p[0], v.p[0]);
                acc[i].p[1] = add2(acc[i].p[1], v.p[1]);
            }
        }

#pragma unroll
        for (int i = 0; i < NPW; i++) {
            u64 sd = dup2(sn[i]);
            acc[i].p[0] = mul2(acc[i].p[0], sd);
            acc[i].p[1] = mul2(acc[i].p[1], sd);
            *(float4*)(us + (w * NPW + i) * CC + lane * 4) = acc[i].v;
        }
    }
    __syncthreads();

    // ---- GEMV: warp (g, half) does nodes [g*8, g*8+8), k in [half*64, half*64+64).
    //      Lane owns outputs 4*lane..4*lane+3. W streamed from global via L1. ----
    const int g    = w & 7;
    const int half = w >> 3;

    u64 a01[GW], a23[GW];
#pragma unroll
    for (int i = 0; i < GW; i++) { a01[i] = 0ull; a23[i] = 0ull; }

    const float* ub = us + (g * GW) * CC;

    for (int c0 = 0; c0 < CC / 2; c0 += 4) {
        const int c = half * (CC / 2) + c0;
        F4 w0, w1, w2, w3;
        w0.v = *(const float4*)(Wt + (size_t)(c + 0) * CC + lane * 4);
        w1.v = *(const float4*)(Wt + (size_t)(c + 1) * CC + lane * 4);
        w2.v = *(const float4*)(Wt + (size_t)(c + 2) * CC + lane * 4);
        w3.v = *(const float4*)(Wt + (size_t)(c + 3) * CC + lane * 4);
#pragma unroll
        for (int i = 0; i < GW; i++) {
            F4 u; u.v = *(const float4*)(ub + i * CC + c);   // broadcast LDS.128
            u64 d0 = dup2(u.f[0]);
            a01[i] = fma2(w0.p[0], d0, a01[i]);
            a23[i] = fma2(w0.p[1], d0, a23[i]);
            u64 d1 = dup2(u.f[1]);
            a01[i] = fma2(w1.p[0], d1, a01[i]);
            a23[i] = fma2(w1.p[1], d1, a23[i]);
            u64 d2 = dup2(u.f[2]);
            a01[i] = fma2(w2.p[0], d2, a01[i]);
            a23[i] = fma2(w2.p[1], d2, a23[i]);
            u64 d3 = dup2(u.f[3]);
            a01[i] = fma2(w3.p[0], d3, a01[i]);
            a23[i] = fma2(w3.p[1], d3, a23[i]);
        }
    }
    __syncthreads();   // all warps done reading us

    // k-half 1 writes partials into the (now dead) us region
    if (half == 1) {
#pragma unroll
        for (int i = 0; i < GW; i++) {
            F4 r; r.p[0] = a01[i]; r.p[1] = a23[i];
            *(float4*)(us + (g * GW + i) * CC + lane * 4) = r.v;
        }
    }
    __syncthreads();

    // k-half 0 reduces, applies ELU (+isd), writes out
    if (half == 0) {
#pragma unroll
        for (int i = 0; i < GW; i++) {
            const int gn = node0 + g * GW + i;
            F4 part; part.v = *(const float4*)(us + (g * GW + i) * CC + lane * 4);
            F4 r0;
            r0.p[0] = add2(a01[i], part.p[0]);
            r0.p[1] = add2(a23[i], part.p[1]);
            F4 r;
            r.f[0] = elu(r0.f[0]);
            r.f[1] = elu(r0.f[1]);
            r.f[2] = elu(r0.f[2]);
            r.f[3] = elu(r0.f[3]);
            if (!LAST) {
                u64 sd = dup2(g_isd[gn]);
                r.p[0] = mul2(r.p[0], sd);
                r.p[1] = mul2(r.p[1], sd);
            }
            *(float4*)(out + (size_t)gn * CC + lane * 4) = r.v;
        }
    }
}

extern "C" void kernel_launch(void* const* d_in, const int* in_sizes, int n_in,
                              void* d_out, int out_size) {
    const float* x    = (const float*)d_in[0];
    const int*   edge = (const int*)d_in[1];
    const float* W0   = (const float*)d_in[2];
    const float* W1   = (const float*)d_in[3];
    const float* W2   = (const float*)d_in[4];
    float* out = (float*)d_out;

    float *bufA = nullptr, *bufB = nullptr, *Wt = nullptr;
    cudaGetSymbolAddress((void**)&bufA, g_bufA);
    cudaGetSymbolAddress((void**)&bufB, g_bufB);
    cudaGetSymbolAddress((void**)&Wt,   g_Wt);

    isd_kernel<<<(BN + 255) / 256, 256>>>(edge);

    const int zthreads = BN * (CC / 4) + (CC / 4);
    zprep_kernel<<<(zthreads + 255) / 256, 256>>>(x);

    wtrans_kernel<<<(3 * CC * CC + 255) / 256, 256>>>(W0, W1, W2);

    const int blocks = BN / NPB;   // 1250
    layer_kernel<false><<<blocks, THREADS>>>(bufA, edge, Wt + 0 * CC * CC, bufB);
    layer_kernel<false><<<blocks, THREADS>>>(bufB, edge, Wt + 1 * CC * CC, bufA);
    layer_kernel<true ><<<blocks, THREADS>>>(bufA, edge, Wt + 2 * CC * CC, out);
}

// round 7
// speedup vs baseline: 1.2729x; 1.2729x over previous
#include <cuda_runtime.h>
#include <math.h>

#define BB 4
#define NN 20000
#define EE 16
#define CC 128
#define BN (BB*NN)

#define THREADS 1024
#define NPW 4                   // gather: nodes per warp (32 warps x 4 = 128)
#define GW  8                   // gemv:   nodes per warp group
#define NPB 128                 // nodes per CTA

typedef unsigned long long u64;
typedef unsigned int u32;

// Scratch (+1 zero pad row at index BN for -1 edges)
__device__ float g_isd[BN];
__device__ float g_bufA[((size_t)BN + 1) * CC];
__device__ float g_bufB[((size_t)BN + 1) * CC];
__device__ float g_Wt[3][CC * CC];   // pre-transposed: Wt[c*128+o] = W[o*128+c]

union F4 { float4 v; u64 p[2]; float f[4]; };
union F2 { double d; u64 p; float f[2]; };

__device__ __forceinline__ u64 fma2(u64 a, u64 b, u64 c) {
    u64 d; asm("fma.rn.f32x2 %0,%1,%2,%3;" : "=l"(d) : "l"(a), "l"(b), "l"(c)); return d;
}
__device__ __forceinline__ u64 add2(u64 a, u64 b) {
    u64 d; asm("add.rn.f32x2 %0,%1,%2;" : "=l"(d) : "l"(a), "l"(b)); return d;
}
__device__ __forceinline__ u64 mul2(u64 a, u64 b) {
    u64 d; asm("mul.rn.f32x2 %0,%1,%2;" : "=l"(d) : "l"(a), "l"(b)); return d;
}
__device__ __forceinline__ u64 dup2(float s) {
    u64 d; asm("mov.b64 %0,{%1,%1};" : "=l"(d) : "f"(s)); return d;
}
__device__ __forceinline__ u32 smem_u32(const void* p) {
    u32 a;
    asm("{ .reg .u64 t; cvta.to.shared.u64 t, %1; cvt.u32.u64 %0, t; }" : "=r"(a) : "l"(p));
    return a;
}
__device__ __forceinline__ float elu(float v) { return v > 0.0f ? v : expm1f(v); }

// ---- prep kernels ----
__global__ void isd_kernel(const int* __restrict__ edge) {
    int g = blockIdx.x * blockDim.x + threadIdx.x;
    if (g >= BN) return;
    const int* e = edge + (size_t)g * EE;
    int d = 1;
#pragma unroll
    for (int i = 0; i < EE; i++) d += (e[i] >= 0);
    g_isd[g] = rsqrtf((float)d);
}

// z0 = x * isd -> bufA; zero pad rows of both buffers
__global__ void zprep_kernel(const float* __restrict__ x) {
    int t = blockIdx.x * blockDim.x + threadIdx.x;   // one float4 per thread
    if (t < BN * (CC / 4)) {
        int row = t >> 5;
        float s = g_isd[row];
        F4 v; v.v = *(const float4*)(x + (size_t)t * 4);
        u64 sd = dup2(s);
        v.p[0] = mul2(v.p[0], sd);
        v.p[1] = mul2(v.p[1], sd);
        *(float4*)(g_bufA + (size_t)t * 4) = v.v;
    } else {
        int r = t - BN * (CC / 4);
        if (r < CC / 4) {
            *(float4*)(g_bufA + (size_t)BN * CC + r * 4) = make_float4(0, 0, 0, 0);
            *(float4*)(g_bufB + (size_t)BN * CC + r * 4) = make_float4(0, 0, 0, 0);
        }
    }
}

// Transpose all three W's once: Wt[l][c*128+o] = W_l[o*128+c]
__global__ void wtrans_kernel(const float* __restrict__ W0,
                              const float* __restrict__ W1,
                              const float* __restrict__ W2) {
    int t = blockIdx.x * blockDim.x + threadIdx.x;
    if (t >= 3 * CC * CC) return;
    int l = t / (CC * CC), i = t % (CC * CC);
    int c = i >> 7, o = i & 127;
    const float* W = (l == 0) ? W0 : (l == 1) ? W1 : W2;
    g_Wt[l][i] = W[o * CC + c];
}

// ---- fused layer ----
// u[n]   = isd[n] * ( z[n] + sum_e z[nbr] )       (z pre-scaled by isd)
// v[n]   = u[n] @ W^T                             (K-split over warp halves)
// out[n] = LAST ? ELU(v) : ELU(v) * isd[n]
template<bool LAST>
__global__ __launch_bounds__(THREADS, 1)
void layer_kernel(const float* __restrict__ zin,
                  const int*   __restrict__ edge,
                  const float* __restrict__ Wt,     // pre-transposed [c][o]
                  float*       __restrict__ out)
{
    extern __shared__ float sm[];
    float* Ws = sm;                   // [128][128] (64 KB)
    float* us = sm + CC * CC;         // [128][128] (64 KB); reused for partials

    const int t = threadIdx.x, w = t >> 5, lane = t & 31;
    const int node0 = blockIdx.x * NPB;

    // ---- Stage W via cp.async (overlaps with gather) ----
    {
        const u32 dst = smem_u32(Ws) + t * 16;
        const float* src = Wt + t * 4;
#pragma unroll
        for (int i = 0; i < (CC * CC) / (THREADS * 4); i++) {
            asm volatile("cp.async.ca.shared.global [%0], [%1], 16;"
                         :: "r"(dst + i * THREADS * 16), "l"(src + i * THREADS * 4));
        }
        asm volatile("cp.async.commit_group;");
    }

    // ---- Gather: warp handles 4 nodes; lane owns channels [4*lane, 4*lane+4) ----
    {
        F4    acc[NPW];
        int   eidx[NPW];
        float sn[NPW];
#pragma unroll
        for (int i = 0; i < NPW; i++) {
            const int gn = node0 + w * NPW + i;
            sn[i] = g_isd[gn];
            int m = -1;
            if (lane < EE) m = edge[(size_t)gn * EE + lane];
            eidx[i] = (m < 0) ? BN : ((gn / NN) * NN + m);
            acc[i].v = *((const float4*)(zin + (size_t)gn * CC) + lane);
        }

#pragma unroll 4
        for (int e = 0; e < EE; e++) {
#pragma unroll
            for (int i = 0; i < NPW; i++) {
                int m = __shfl_sync(0xffffffffu, eidx[i], e);
                F4 v; v.v = *((const float4*)(zin + (size_t)m * CC) + lane);
                acc[i].p[0] = add2(acc[i].p[0], v.p[0]);
                acc[i].p[1] = add2(acc[i].p[1], v.p[1]);
            }
        }

#pragma unroll
        for (int i = 0; i < NPW; i++) {
            u64 sd = dup2(sn[i]);
            acc[i].p[0] = mul2(acc[i].p[0], sd);
            acc[i].p[1] = mul2(acc[i].p[1], sd);
            *(float4*)(us + (w * NPW + i) * CC + lane * 4) = acc[i].v;
        }
    }
    asm volatile("cp.async.wait_group 0;" ::: "memory");
    __syncthreads();

    // ---- GEMV: warp (g, half): nodes [g*8, g*8+8), k in [half*64, half*64+64).
    //      Lane owns outputs 4*lane..4*lane+3. W from smem. ----
    const int g    = w & 15;
    const int half = w >> 4;

    u64 a01[GW], a23[GW];
#pragma unroll
    for (int i = 0; i < GW; i++) { a01[i] = 0ull; a23[i] = 0ull; }

    const float* ub = us + (g * GW) * CC + half * (CC / 2);
    const float* Wb = Ws + half * (CC / 2) * CC + lane * 4;

    for (int c = 0; c < CC / 2; c += 2) {
        F4 w0, w1;
        w0.v = *(const float4*)(Wb + (c + 0) * CC);
        w1.v = *(const float4*)(Wb + (c + 1) * CC);
#pragma unroll
        for (int i = 0; i < GW; i++) {
            F2 u; u.d = *(const double*)(ub + i * CC + c);   // LDS.64 broadcast
            u64 d0 = dup2(u.f[0]);
            a01[i] = fma2(w0.p[0], d0, a01[i]);
            a23[i] = fma2(w0.p[1], d0, a23[i]);
            u64 d1 = dup2(u.f[1]);
            a01[i] = fma2(w1.p[0], d1, a01[i]);
            a23[i] = fma2(w1.p[1], d1, a23[i]);
        }
    }
    __syncthreads();   // everyone done reading us

    // k-half 1 parks partials in the dead us region
    if (half == 1) {
#pragma unroll
        for (int i = 0; i < GW; i++) {
            F4 r; r.p[0] = a01[i]; r.p[1] = a23[i];
            *(float4*)(us + (g * GW + i) * CC + lane * 4) = r.v;
        }
    }
    __syncthreads();

    // k-half 0 reduces, applies ELU (+isd), writes out
    if (half == 0) {
#pragma unroll
        for (int i = 0; i < GW; i++) {
            const int gn = node0 + g * GW + i;
            F4 part; part.v = *(const float4*)(us + (g * GW + i) * CC + lane * 4);
            F4 r0;
            r0.p[0] = add2(a01[i], part.p[0]);
            r0.p[1] = add2(a23[i], part.p[1]);
            F4 r;
            r.f[0] = elu(r0.f[0]);
            r.f[1] = elu(r0.f[1]);
            r.f[2] = elu(r0.f[2]);
            r.f[3] = elu(r0.f[3]);
            if (!LAST) {
                u64 sd = dup2(g_isd[gn]);
                r.p[0] = mul2(r.p[0], sd);
                r.p[1] = mul2(r.p[1], sd);
            }
            *(float4*)(out + (size_t)gn * CC + lane * 4) = r.v;
        }
    }
}

extern "C" void kernel_launch(void* const* d_in, const int* in_sizes, int n_in,
                              void* d_out, int out_size) {
    const float* x    = (const float*)d_in[0];
    const int*   edge = (const int*)d_in[1];
    const float* W0   = (const float*)d_in[2];
    const float* W1   = (const float*)d_in[3];
    const float* W2   = (const float*)d_in[4];
    float* out = (float*)d_out;

    float *bufA = nullptr, *bufB = nullptr, *Wt = nullptr;
    cudaGetSymbolAddress((void**)&bufA, g_bufA);
    cudaGetSymbolAddress((void**)&bufB, g_bufB);
    cudaGetSymbolAddress((void**)&Wt,   g_Wt);

    const int smem_bytes = 2 * CC * CC * sizeof(float);   // 131072
    cudaFuncSetAttribute(layer_kernel<false>,
                         cudaFuncAttributeMaxDynamicSharedMemorySize, smem_bytes);
    cudaFuncSetAttribute(layer_kernel<true>,
                         cudaFuncAttributeMaxDynamicSharedMemorySize, smem_bytes);

    isd_kernel<<<(BN + 255) / 256, 256>>>(edge);

    const int zthreads = BN * (CC / 4) + (CC / 4);
    zprep_kernel<<<(zthreads + 255) / 256, 256>>>(x);

    wtrans_kernel<<<(3 * CC * CC + 255) / 256, 256>>>(W0, W1, W2);

    const int blocks = BN / NPB;   // 625
    layer_kernel<false><<<blocks, THREADS, smem_bytes>>>(bufA, edge, Wt + 0 * CC * CC, bufB);
    layer_kernel<false><<<blocks, THREADS, smem_bytes>>>(bufB, edge, Wt + 1 * CC * CC, bufA);
    layer_kernel<true ><<<blocks, THREADS, smem_bytes>>>(bufA, edge, Wt + 2 * CC * CC, out);
}

// round 8
// speedup vs baseline: 1.5309x; 1.2027x over previous
#include <cuda_runtime.h>
#include <math.h>

#define BB 4
#define NN 20000
#define EE 16
#define CC 128
#define BN (BB*NN)

#define THREADS 1024
#define TILE 128               // nodes per tile
#define NTILES (BN / TILE)     // 625
#define GRID 148

typedef unsigned long long u64;
typedef unsigned int u32;

// Scratch (+1 zero pad row at index BN for -1 edges)
__device__ float g_isd[BN];
__device__ float g_bufA[((size_t)BN + 1) * CC];
__device__ float g_bufB[((size_t)BN + 1) * CC];
__device__ float g_Wt[3][CC * CC];   // pre-transposed: Wt[c*128+o] = W[o*128+c]

union F4 { float4 v; u64 p[2]; float f[4]; };

__device__ __forceinline__ u64 fma2(u64 a, u64 b, u64 c) {
    u64 d; asm("fma.rn.f32x2 %0,%1,%2,%3;" : "=l"(d) : "l"(a), "l"(b), "l"(c)); return d;
}
__device__ __forceinline__ u64 add2(u64 a, u64 b) {
    u64 d; asm("add.rn.f32x2 %0,%1,%2;" : "=l"(d) : "l"(a), "l"(b)); return d;
}
__device__ __forceinline__ u64 mul2(u64 a, u64 b) {
    u64 d; asm("mul.rn.f32x2 %0,%1,%2;" : "=l"(d) : "l"(a), "l"(b)); return d;
}
__device__ __forceinline__ u64 dup2(float s) {
    u64 d; asm("mov.b64 %0,{%1,%1};" : "=l"(d) : "f"(s)); return d;
}
__device__ __forceinline__ u32 smem_u32(const void* p) {
    u32 a;
    asm("{ .reg .u64 t; cvta.to.shared.u64 t, %1; cvt.u32.u64 %0, t; }" : "=r"(a) : "l"(p));
    return a;
}
__device__ __forceinline__ float elu(float v) { return v > 0.0f ? v : expm1f(v); }

#define BAR_SYNC(id)   asm volatile("bar.sync %0, %1;"   :: "r"(id), "r"(THREADS) : "memory")
#define BAR_ARRIVE(id) asm volatile("bar.arrive %0, %1;" :: "r"(id), "r"(THREADS) : "memory")
// ids: FULL[b] = 1+b, EMPTY[b] = 3+b

// ---- prep kernels ----
__global__ void isd_kernel(const int* __restrict__ edge) {
    int g = blockIdx.x * blockDim.x + threadIdx.x;
    if (g >= BN) return;
    const int* e = edge + (size_t)g * EE;
    int d = 1;
#pragma unroll
    for (int i = 0; i < EE; i++) d += (e[i] >= 0);
    g_isd[g] = rsqrtf((float)d);
}

__global__ void zprep_kernel(const float* __restrict__ x) {
    int t = blockIdx.x * blockDim.x + threadIdx.x;   // one float4 per thread
    if (t < BN * (CC / 4)) {
        int row = t >> 5;
        float s = g_isd[row];
        F4 v; v.v = *(const float4*)(x + (size_t)t * 4);
        u64 sd = dup2(s);
        v.p[0] = mul2(v.p[0], sd);
        v.p[1] = mul2(v.p[1], sd);
        *(float4*)(g_bufA + (size_t)t * 4) = v.v;
    } else {
        int r = t - BN * (CC / 4);
        if (r < CC / 4) {
            *(float4*)(g_bufA + (size_t)BN * CC + r * 4) = make_float4(0, 0, 0, 0);
            *(float4*)(g_bufB + (size_t)BN * CC + r * 4) = make_float4(0, 0, 0, 0);
        }
    }
}

__global__ void wtrans_kernel(const float* __restrict__ W0,
                              const float* __restrict__ W1,
                              const float* __restrict__ W2) {
    int t = blockIdx.x * blockDim.x + threadIdx.x;
    if (t >= 3 * CC * CC) return;
    int l = t / (CC * CC), i = t % (CC * CC);
    int c = i >> 7, o = i & 127;
    const float* W = (l == 0) ? W0 : (l == 1) ? W1 : W2;
    g_Wt[l][i] = W[o * CC + c];
}

// ---- fused layer: producer warps gather, consumer warps GEMV+ELU ----
template<bool LAST>
__global__ __launch_bounds__(THREADS, 1)
void layer_kernel(const float* __restrict__ zin,
                  const int*   __restrict__ edge,
                  const float* __restrict__ Wt,     // pre-transposed [c][o]
                  float*       __restrict__ out)
{
    extern __shared__ float sm[];
    float* Ws = sm;                           // [128][128]  64 KB
    float* usb = sm + CC * CC;                // 2 x [128][128]  (double buffer)

    const int t = threadIdx.x, w = t >> 5, lane = t & 31;

    // Stage W once via cp.async
    {
        const u32 dst = smem_u32(Ws);
#pragma unroll
        for (int i = 0; i < (CC * CC) / (THREADS * 4); i++) {
            int idx = t + i * THREADS;
            asm volatile("cp.async.ca.shared.global [%0], [%1], 16;"
                         :: "r"(dst + idx * 16), "l"(Wt + idx * 4));
        }
        asm volatile("cp.async.commit_group;");
        asm volatile("cp.async.wait_group 0;" ::: "memory");
    }
    __syncthreads();

    int it = 0;
    for (int tile = blockIdx.x; tile < NTILES; tile += GRID, it++) {
        const int buf = it & 1;
        float* ub = usb + buf * (TILE * CC);
        const int node0 = tile * TILE;

        if (w < 16) {
            // ---------------- producer: gather 8 nodes (2 groups of 4) -------
            if (it >= 2) BAR_SYNC(3 + buf);          // wait buffer empty
#pragma unroll
            for (int h = 0; h < 2; h++) {
                F4    acc[4];
                int   eidx[4];
                float sn[4];
                const int gbase = node0 + w * 8 + h * 4;
#pragma unroll
                for (int i = 0; i < 4; i++) {
                    const int gn = gbase + i;
                    sn[i] = g_isd[gn];
                    int m = -1;
                    if (lane < EE) m = edge[(size_t)gn * EE + lane];
                    eidx[i] = (m < 0) ? BN : ((gn / NN) * NN + m);
                    acc[i].v = *((const float4*)(zin + (size_t)gn * CC) + lane);
                }
#pragma unroll 4
                for (int e = 0; e < EE; e++) {
#pragma unroll
                    for (int i = 0; i < 4; i++) {
                        int m = __shfl_sync(0xffffffffu, eidx[i], e);
                        F4 v; v.v = *((const float4*)(zin + (size_t)m * CC) + lane);
                        acc[i].p[0] = add2(acc[i].p[0], v.p[0]);
                        acc[i].p[1] = add2(acc[i].p[1], v.p[1]);
                    }
                }
#pragma unroll
                for (int i = 0; i < 4; i++) {
                    u64 sd = dup2(sn[i]);
                    acc[i].p[0] = mul2(acc[i].p[0], sd);
                    acc[i].p[1] = mul2(acc[i].p[1], sd);
                    *(float4*)(ub + (w * 8 + h * 4 + i) * CC + lane * 4) = acc[i].v;
                }
            }
            BAR_ARRIVE(1 + buf);                     // signal buffer full
        } else {
            // ---------------- consumer: GEMV 8 nodes + epilogue --------------
            BAR_SYNC(1 + buf);                       // wait buffer full
            const int cw = w - 16;
            const float* ubase = ub + (cw * 8) * CC;

            u64 a01[8], a23[8];
#pragma unroll
            for (int i = 0; i < 8; i++) { a01[i] = 0ull; a23[i] = 0ull; }

            for (int c = 0; c < CC; c += 4) {
                F4 w0, w1, w2, w3;
                w0.v = *(const float4*)(Ws + (c + 0) * CC + lane * 4);
                w1.v = *(const float4*)(Ws + (c + 1) * CC + lane * 4);
                w2.v = *(const float4*)(Ws + (c + 2) * CC + lane * 4);
                w3.v = *(const float4*)(Ws + (c + 3) * CC + lane * 4);
#pragma unroll
                for (int i = 0; i < 8; i++) {
                    F4 u; u.v = *(const float4*)(ubase + i * CC + c);
                    u64 d0 = dup2(u.f[0]);
                    a01[i] = fma2(w0.p[0], d0, a01[i]);
                    a23[i] = fma2(w0.p[1], d0, a23[i]);
                    u64 d1 = dup2(u.f[1]);
                    a01[i] = fma2(w1.p[0], d1, a01[i]);
                    a23[i] = fma2(w1.p[1], d1, a23[i]);
                    u64 d2 = dup2(u.f[2]);
                    a01[i] = fma2(w2.p[0], d2, a01[i]);
                    a23[i] = fma2(w2.p[1], d2, a23[i]);
                    u64 d3 = dup2(u.f[3]);
                    a01[i] = fma2(w3.p[0], d3, a01[i]);
                    a23[i] = fma2(w3.p[1], d3, a23[i]);
                }
            }
            BAR_ARRIVE(3 + buf);                     // buffer free for producer

#pragma unroll
            for (int i = 0; i < 8; i++) {
                const int gn = node0 + cw * 8 + i;
                F4 r0; r0.p[0] = a01[i]; r0.p[1] = a23[i];
                F4 r;
                r.f[0] = elu(r0.f[0]);
                r.f[1] = elu(r0.f[1]);
                r.f[2] = elu(r0.f[2]);
                r.f[3] = elu(r0.f[3]);
                if (!LAST) {
                    u64 sd = dup2(g_isd[gn]);
                    r.p[0] = mul2(r.p[0], sd);
                    r.p[1] = mul2(r.p[1], sd);
                }
                *(float4*)(out + (size_t)gn * CC + lane * 4) = r.v;
            }
        }
    }
}

extern "C" void kernel_launch(void* const* d_in, const int* in_sizes, int n_in,
                              void* d_out, int out_size) {
    const float* x    = (const float*)d_in[0];
    const int*   edge = (const int*)d_in[1];
    const float* W0   = (const float*)d_in[2];
    const float* W1   = (const float*)d_in[3];
    const float* W2   = (const float*)d_in[4];
    float* out = (float*)d_out;

    float *bufA = nullptr, *bufB = nullptr, *Wt = nullptr;
    cudaGetSymbolAddress((void**)&bufA, g_bufA);
    cudaGetSymbolAddress((void**)&bufB, g_bufB);
    cudaGetSymbolAddress((void**)&Wt,   g_Wt);

    const int smem_bytes = (CC * CC + 2 * TILE * CC) * sizeof(float);   // 196608
    cudaFuncSetAttribute(layer_kernel<false>,
                         cudaFuncAttributeMaxDynamicSharedMemorySize, smem_bytes);
    cudaFuncSetAttribute(layer_kernel<true>,
                         cudaFuncAttributeMaxDynamicSharedMemorySize, smem_bytes);

    isd_kernel<<<(BN + 255) / 256, 256>>>(edge);

    const int zthreads = BN * (CC / 4) + (CC / 4);
    zprep_kernel<<<(zthreads + 255) / 256, 256>>>(x);

    wtrans_kernel<<<(3 * CC * CC + 255) / 256, 256>>>(W0, W1, W2);

    layer_kernel<false><<<GRID, THREADS, smem_bytes>>>(bufA, edge, Wt + 0 * CC * CC, bufB);
    layer_kernel<false><<<GRID, THREADS, smem_bytes>>>(bufB, edge, Wt + 1 * CC * CC, bufA);
    layer_kernel<true ><<<GRID, THREADS, smem_bytes>>>(bufA, edge, Wt + 2 * CC * CC, out);
}

// round 10
// speedup vs baseline: 1.5733x; 1.0277x over previous
#include <cuda_runtime.h>
#include <math.h>

#define BB 4
#define NN 20000
#define EE 16
#define CC 128
#define BN (BB*NN)

#define THREADS 512
#define TILE 128
#define NTILES (BN / TILE)     // 625
#define GRID 148
#define USTRIDE 132            // us row stride (pad): conflict-free frag LDS

typedef unsigned long long u64;
typedef unsigned int u32;

// Scratch (+1 zero pad row at index BN for -1 edges)
__device__ float g_isd[BN];
__device__ float g_bufA[((size_t)BN + 1) * CC];
__device__ float g_bufB[((size_t)BN + 1) * CC];
// B fragments in mma lane order: [layer][ks(16)][nb(16)][lane(32)] float2 (b0,b1)
__device__ float2 g_Wfh[3 * 16 * 16 * 32];
__device__ float2 g_Wfl[3 * 16 * 16 * 32];

union F4 { float4 v; u64 p[2]; float f[4]; };

__device__ __forceinline__ u64 add2(u64 a, u64 b) {
    u64 d; asm("add.rn.f32x2 %0,%1,%2;" : "=l"(d) : "l"(a), "l"(b)); return d;
}
__device__ __forceinline__ u64 mul2(u64 a, u64 b) {
    u64 d; asm("mul.rn.f32x2 %0,%1,%2;" : "=l"(d) : "l"(a), "l"(b)); return d;
}
__device__ __forceinline__ u64 dup2(float s) {
    u64 d; asm("mov.b64 %0,{%1,%1};" : "=l"(d) : "f"(s)); return d;
}
__device__ __forceinline__ u32 tf32cvt(float f) {
    u32 r; asm("cvt.rna.tf32.f32 %0,%1;" : "=r"(r) : "f"(f)); return r;
}
__device__ __forceinline__ u32 smem_u32(const void* p) {
    u32 a;
    asm("{ .reg .u64 t; cvta.to.shared.u64 t, %1; cvt.u32.u64 %0, t; }" : "=r"(a) : "l"(p));
    return a;
}
__device__ __forceinline__ float elu(float v) { return v > 0.0f ? v : expm1f(v); }

// D(16x8,f32) += A(16x8,tf32,row) * B(8x8,tf32,col)
__device__ __forceinline__ void mma8(float* c, const u32* a, u32 b0, u32 b1) {
    asm("mma.sync.aligned.m16n8k8.row.col.f32.tf32.tf32.f32 "
        "{%0,%1,%2,%3}, {%4,%5,%6,%7}, {%8,%9}, {%0,%1,%2,%3};"
        : "+f"(c[0]), "+f"(c[1]), "+f"(c[2]), "+f"(c[3])
        : "r"(a[0]), "r"(a[1]), "r"(a[2]), "r"(a[3]), "r"(b0), "r"(b1));
}

// ---- prep kernels ----
__global__ void isd_kernel(const int* __restrict__ edge) {
    int g = blockIdx.x * blockDim.x + threadIdx.x;
    if (g >= BN) return;
    const int* e = edge + (size_t)g * EE;
    int d = 1;
#pragma unroll
    for (int i = 0; i < EE; i++) d += (e[i] >= 0);
    g_isd[g] = rsqrtf((float)d);
}

__global__ void zprep_kernel(const float* __restrict__ x) {
    int t = blockIdx.x * blockDim.x + threadIdx.x;   // one float4 per thread
    if (t < BN * (CC / 4)) {
        int row = t >> 5;
        float s = g_isd[row];
        F4 v; v.v = *(const float4*)(x + (size_t)t * 4);
        u64 sd = dup2(s);
        v.p[0] = mul2(v.p[0], sd);
        v.p[1] = mul2(v.p[1], sd);
        *(float4*)(g_bufA + (size_t)t * 4) = v.v;
    } else {
        int r = t - BN * (CC / 4);
        if (r < CC / 4) {
            *(float4*)(g_bufA + (size_t)BN * CC + r * 4) = make_float4(0, 0, 0, 0);
            *(float4*)(g_bufB + (size_t)BN * CC + r * 4) = make_float4(0, 0, 0, 0);
        }
    }
}

// Pack W into mma B-fragment order, hi/lo tf32 split.
// B block (ks, nb): k in [8ks,8ks+8), n in [8nb,8nb+8).
// lane: gid=lane>>2, tid=lane&3. b0 = B[k=tid][n=gid], b1 = B[k=tid+4][n=gid].
// B[k][n] = W[n][k]  (V = U @ W^T).
__global__ void wfrag_kernel(const float* __restrict__ W0,
                             const float* __restrict__ W1,
                             const float* __restrict__ W2) {
    int t = blockIdx.x * blockDim.x + threadIdx.x;
    if (t >= 3 * 16 * 16 * 32) return;
    int lane = t & 31;
    int nb   = (t >> 5) & 15;
    int ks   = (t >> 9) & 15;
    int l    = t >> 13;
    int gid = lane >> 2, tid = lane & 3;
    const float* W = (l == 0) ? W0 : (l == 1) ? W1 : W2;
    float v0 = W[(8 * nb + gid) * CC + (8 * ks + tid)];
    float v1 = W[(8 * nb + gid) * CC + (8 * ks + tid + 4)];
    u32 h0 = tf32cvt(v0), h1 = tf32cvt(v1);
    float2 hi, lo;
    hi.x = __uint_as_float(h0);
    hi.y = __uint_as_float(h1);
    lo.x = __uint_as_float(tf32cvt(v0 - hi.x));
    lo.y = __uint_as_float(tf32cvt(v1 - hi.y));
    g_Wfh[t] = hi;
    g_Wfl[t] = lo;
}

// ---- fused layer: gather -> smem us; tf32 mma GEMM; ELU epilogue ----
template<bool LAST>
__global__ __launch_bounds__(THREADS, 1)
void layer_kernel(const float* __restrict__ zin,
                  const int*   __restrict__ edge,
                  const float2* __restrict__ Wfh,
                  const float2* __restrict__ Wfl,
                  float*       __restrict__ out)
{
    extern __shared__ float sm[];
    float2* Wfh_s = (float2*)sm;                          // 8192 float2 (64 KB)
    float2* Wfl_s = Wfh_s + 16 * 16 * 32;                 // 8192 float2 (64 KB)
    float*  us    = (float*)(Wfl_s + 16 * 16 * 32);       // [128][132]
    float*  isd_s = us + TILE * USTRIDE;                  // [128]

    const int t = threadIdx.x, w = t >> 5, lane = t & 31;
    const int gid = lane >> 2, tid = lane & 3;

    // Stage W fragments once (cp.async). 64 KB per array = 4096 x 16B chunks.
    {
        const u32 dh = smem_u32(Wfh_s), dl = smem_u32(Wfl_s);
#pragma unroll
        for (int i = 0; i < 4096 / THREADS; i++) {      // 8 iterations
            int idx = t + i * THREADS;
            asm volatile("cp.async.ca.shared.global [%0], [%1], 16;"
                         :: "r"(dh + idx * 16), "l"((const char*)Wfh + idx * 16));
            asm volatile("cp.async.ca.shared.global [%0], [%1], 16;"
                         :: "r"(dl + idx * 16), "l"((const char*)Wfl + idx * 16));
        }
        asm volatile("cp.async.commit_group;");
        asm volatile("cp.async.wait_group 0;" ::: "memory");
    }
    __syncthreads();

    const int wm = w & 3, wn = w >> 2;   // warp grid 4x4, tile 32x32
    const int m0 = wm * 32;

    for (int tile = blockIdx.x; tile < NTILES; tile += GRID) {
        const int node0 = tile * TILE;

        // ---- Gather: warp handles 8 nodes; lane owns channels [4*lane, +4) ----
        {
            F4    acc[8];
            int   eidx[8];
            float sn[8];
#pragma unroll
            for (int i = 0; i < 8; i++) {
                const int gn = node0 + w * 8 + i;
                sn[i] = g_isd[gn];
                int m = -1;
                if (lane < EE) m = edge[(size_t)gn * EE + lane];
                eidx[i] = (m < 0) ? BN : ((gn / NN) * NN + m);
                acc[i].v = *((const float4*)(zin + (size_t)gn * CC) + lane);
            }
#pragma unroll 2
            for (int e = 0; e < EE; e++) {
#pragma unroll
                for (int i = 0; i < 8; i++) {
                    int m = __shfl_sync(0xffffffffu, eidx[i], e);
                    F4 v; v.v = *((const float4*)(zin + (size_t)m * CC) + lane);
                    acc[i].p[0] = add2(acc[i].p[0], v.p[0]);
                    acc[i].p[1] = add2(acc[i].p[1], v.p[1]);
                }
            }
#pragma unroll
            for (int i = 0; i < 8; i++) {
                u64 sd = dup2(sn[i]);
                acc[i].p[0] = mul2(acc[i].p[0], sd);
                acc[i].p[1] = mul2(acc[i].p[1], sd);
                *(float4*)(us + (w * 8 + i) * USTRIDE + lane * 4) = acc[i].v;
            }
            if (t < TILE) isd_s[t] = g_isd[node0 + t];
        }
        __syncthreads();

        // ---- GEMM: warp computes V[m0..m0+32)[32*wn..+32), K=128 ----
        float acc[2][4][4];
#pragma unroll
        for (int f = 0; f < 2; f++)
#pragma unroll
            for (int g = 0; g < 4; g++)
#pragma unroll
                for (int j = 0; j < 4; j++) acc[f][g][j] = 0.0f;

        for (int ks = 0; ks < 16; ks++) {
            const int k0 = ks * 8;
            u32 ah[2][4], al[2][4];
#pragma unroll
            for (int f = 0; f < 2; f++) {
                const float* ub = us + (m0 + 16 * f + gid) * USTRIDE + k0 + tid;
                float x0 = ub[0];
                float x1 = ub[8 * USTRIDE];
                float x2 = ub[4];
                float x3 = ub[8 * USTRIDE + 4];
                ah[f][0] = tf32cvt(x0); al[f][0] = tf32cvt(x0 - __uint_as_float(ah[f][0]));
                ah[f][1] = tf32cvt(x1); al[f][1] = tf32cvt(x1 - __uint_as_float(ah[f][1]));
                ah[f][2] = tf32cvt(x2); al[f][2] = tf32cvt(x2 - __uint_as_float(ah[f][2]));
                ah[f][3] = tf32cvt(x3); al[f][3] = tf32cvt(x3 - __uint_as_float(ah[f][3]));
            }
#pragma unroll
            for (int g = 0; g < 4; g++) {
                const int nb = wn * 4 + g;
                float2 bh = Wfh_s[(ks * 16 + nb) * 32 + lane];
                float2 bl = Wfl_s[(ks * 16 + nb) * 32 + lane];
                u32 bh0 = __float_as_uint(bh.x), bh1 = __float_as_uint(bh.y);
                u32 bl0 = __float_as_uint(bl.x), bl1 = __float_as_uint(bl.y);
#pragma unroll
                for (int f = 0; f < 2; f++) {
                    mma8(acc[f][g], ah[f], bh0, bh1);
                    mma8(acc[f][g], al[f], bh0, bh1);
                    mma8(acc[f][g], ah[f], bl0, bl1);
                }
            }
        }

        // ---- Epilogue: ELU (+isd), float2 stores ----
#pragma unroll
        for (int f = 0; f < 2; f++) {
            const int r0 = m0 + 16 * f + gid;
#pragma unroll
            for (int g = 0; g < 4; g++) {
                const int c = wn * 32 + g * 8 + 2 * tid;
                float2 v0, v1;
                v0.x = elu(acc[f][g][0]); v0.y = elu(acc[f][g][1]);
                v1.x = elu(acc[f][g][2]); v1.y = elu(acc[f][g][3]);
                if (!LAST) {
                    float s0 = isd_s[r0], s1 = isd_s[r0 + 8];
                    v0.x *= s0; v0.y *= s0;
                    v1.x *= s1; v1.y *= s1;
                }
                *(float2*)(out + (size_t)(node0 + r0) * CC + c) = v0;
                *(float2*)(out + (size_t)(node0 + r0 + 8) * CC + c) = v1;
            }
        }
        __syncthreads();   // us free for next tile's gather
    }
}

extern "C" void kernel_launch(void* const* d_in, const int* in_sizes, int n_in,
                              void* d_out, int out_size) {
    const float* x    = (const float*)d_in[0];
    const int*   edge = (const int*)d_in[1];
    const float* W0   = (const float*)d_in[2];
    const float* W1   = (const float*)d_in[3];
    const float* W2   = (const float*)d_in[4];
    float* out = (float*)d_out;

    float *bufA = nullptr, *bufB = nullptr;
    float2 *Wfh = nullptr, *Wfl = nullptr;
    cudaGetSymbolAddress((void**)&bufA, g_bufA);
    cudaGetSymbolAddress((void**)&bufB, g_bufB);
    cudaGetSymbolAddress((void**)&Wfh,  g_Wfh);
    cudaGetSymbolAddress((void**)&Wfl,  g_Wfl);

    const int smem_bytes = (2 * 16 * 16 * 32 * 2 + TILE * USTRIDE + TILE) * sizeof(float);
    cudaFuncSetAttribute(layer_kernel<false>,
                         cudaFuncAttributeMaxDynamicSharedMemorySize, smem_bytes);
    cudaFuncSetAttribute(layer_kernel<true>,
                         cudaFuncAttributeMaxDynamicSharedMemorySize, smem_bytes);

    isd_kernel<<<(BN + 255) / 256, 256>>>(edge);

    const int zthreads = BN * (CC / 4) + (CC / 4);
    zprep_kernel<<<(zthreads + 255) / 256, 256>>>(x);

    wfrag_kernel<<<(3 * 16 * 16 * 32 + 255) / 256, 256>>>(W0, W1, W2);

    const int FS = 16 * 16 * 32;   // frags per layer
    layer_kernel<false><<<GRID, THREADS, smem_bytes>>>(bufA, edge, Wfh + 0 * FS, Wfl + 0 * FS, bufB);
    layer_kernel<false><<<GRID, THREADS, smem_bytes>>>(bufB, edge, Wfh + 1 * FS, Wfl + 1 * FS, bufA);
    layer_kernel<true ><<<GRID, THREADS, smem_bytes>>>(bufA, edge, Wfh + 2 * FS, Wfl + 2 * FS, out);
}

// round 11
// speedup vs baseline: 1.6983x; 1.0794x over previous
#include <cuda_runtime.h>
#include <math.h>

#define BB 4
#define NN 20000
#define EE 16
#define CC 128
#define BN (BB*NN)

#define THREADS 1024
#define TILE 128
#define NTILES (BN / TILE)     // 625
#define GRID 148
#define USTRIDE 132            // us row stride (pad): conflict-free frag LDS

typedef unsigned long long u64;
typedef unsigned int u32;

// Scratch (+1 zero pad row at index BN for -1 edges)
__device__ float g_isd[BN];
__device__ float g_bufA[((size_t)BN + 1) * CC];
__device__ float g_bufB[((size_t)BN + 1) * CC];
// B fragments in mma lane order: [layer][ks(16)][nb(16)][lane(32)] float2 (b0,b1)
__device__ float2 g_Wfh[3 * 16 * 16 * 32];
__device__ float2 g_Wfl[3 * 16 * 16 * 32];

union F4 { float4 v; u64 p[2]; float f[4]; };

__device__ __forceinline__ u64 add2(u64 a, u64 b) {
    u64 d; asm("add.rn.f32x2 %0,%1,%2;" : "=l"(d) : "l"(a), "l"(b)); return d;
}
__device__ __forceinline__ u64 mul2(u64 a, u64 b) {
    u64 d; asm("mul.rn.f32x2 %0,%1,%2;" : "=l"(d) : "l"(a), "l"(b)); return d;
}
__device__ __forceinline__ u64 dup2(float s) {
    u64 d; asm("mov.b64 %0,{%1,%1};" : "=l"(d) : "f"(s)); return d;
}
__device__ __forceinline__ u32 tf32cvt(float f) {
    u32 r; asm("cvt.rna.tf32.f32 %0,%1;" : "=r"(r) : "f"(f)); return r;
}
__device__ __forceinline__ u32 smem_u32(const void* p) {
    u32 a;
    asm("{ .reg .u64 t; cvta.to.shared.u64 t, %1; cvt.u32.u64 %0, t; }" : "=r"(a) : "l"(p));
    return a;
}
__device__ __forceinline__ float elu(float v) { return v > 0.0f ? v : expm1f(v); }

// D(16x8,f32) += A(16x8,tf32,row) * B(8x8,tf32,col)
__device__ __forceinline__ void mma8(float* c, const u32* a, u32 b0, u32 b1) {
    asm("mma.sync.aligned.m16n8k8.row.col.f32.tf32.tf32.f32 "
        "{%0,%1,%2,%3}, {%4,%5,%6,%7}, {%8,%9}, {%0,%1,%2,%3};"
        : "+f"(c[0]), "+f"(c[1]), "+f"(c[2]), "+f"(c[3])
        : "r"(a[0]), "r"(a[1]), "r"(a[2]), "r"(a[3]), "r"(b0), "r"(b1));
}

// ---- prep kernels ----
__global__ void isd_kernel(const int* __restrict__ edge) {
    int g = blockIdx.x * blockDim.x + threadIdx.x;
    if (g >= BN) return;
    const int* e = edge + (size_t)g * EE;
    int d = 1;
#pragma unroll
    for (int i = 0; i < EE; i++) d += (e[i] >= 0);
    g_isd[g] = rsqrtf((float)d);
}

__global__ void zprep_kernel(const float* __restrict__ x) {
    int t = blockIdx.x * blockDim.x + threadIdx.x;   // one float4 per thread
    if (t < BN * (CC / 4)) {
        int row = t >> 5;
        float s = g_isd[row];
        F4 v; v.v = *(const float4*)(x + (size_t)t * 4);
        u64 sd = dup2(s);
        v.p[0] = mul2(v.p[0], sd);
        v.p[1] = mul2(v.p[1], sd);
        *(float4*)(g_bufA + (size_t)t * 4) = v.v;
    } else {
        int r = t - BN * (CC / 4);
        if (r < CC / 4) {
            *(float4*)(g_bufA + (size_t)BN * CC + r * 4) = make_float4(0, 0, 0, 0);
            *(float4*)(g_bufB + (size_t)BN * CC + r * 4) = make_float4(0, 0, 0, 0);
        }
    }
}

// Pack W into mma B-fragment order, hi/lo tf32 split.
// B block (ks, nb): k in [8ks,8ks+8), n in [8nb,8nb+8).
// lane: gid=lane>>2, tid=lane&3. b0 = B[k=tid][n=gid], b1 = B[k=tid+4][n=gid].
// B[k][n] = W[n][k]  (V = U @ W^T).
__global__ void wfrag_kernel(const float* __restrict__ W0,
                             const float* __restrict__ W1,
                             const float* __restrict__ W2) {
    int t = blockIdx.x * blockDim.x + threadIdx.x;
    if (t >= 3 * 16 * 16 * 32) return;
    int lane = t & 31;
    int nb   = (t >> 5) & 15;
    int ks   = (t >> 9) & 15;
    int l    = t >> 13;
    int gid = lane >> 2, tid = lane & 3;
    const float* W = (l == 0) ? W0 : (l == 1) ? W1 : W2;
    float v0 = W[(8 * nb + gid) * CC + (8 * ks + tid)];
    float v1 = W[(8 * nb + gid) * CC + (8 * ks + tid + 4)];
    u32 h0 = tf32cvt(v0), h1 = tf32cvt(v1);
    float2 hi, lo;
    hi.x = __uint_as_float(h0);
    hi.y = __uint_as_float(h1);
    lo.x = __uint_as_float(tf32cvt(v0 - hi.x));
    lo.y = __uint_as_float(tf32cvt(v1 - hi.y));
    g_Wfh[t] = hi;
    g_Wfl[t] = lo;
}

// ---- fused layer: gather -> smem us; tf32 mma GEMM; ELU epilogue ----
template<bool LAST>
__global__ __launch_bounds__(THREADS, 1)
void layer_kernel(const float* __restrict__ zin,
                  const int*   __restrict__ edge,
                  const float2* __restrict__ Wfh,
                  const float2* __restrict__ Wfl,
                  float*       __restrict__ out)
{
    extern __shared__ float sm[];
    float2* Wfh_s = (float2*)sm;                          // 8192 float2 (64 KB)
    float2* Wfl_s = Wfh_s + 16 * 16 * 32;                 // 8192 float2 (64 KB)
    float*  us    = (float*)(Wfl_s + 16 * 16 * 32);       // [128][132]
    float*  isd_s = us + TILE * USTRIDE;                  // [128]

    const int t = threadIdx.x, w = t >> 5, lane = t & 31;
    const int gid = lane >> 2, tid = lane & 3;

    // Stage W fragments once (cp.async). 64 KB per array = 4096 x 16B chunks.
    {
        const u32 dh = smem_u32(Wfh_s), dl = smem_u32(Wfl_s);
#pragma unroll
        for (int i = 0; i < 4096 / THREADS; i++) {
            int idx = t + i * THREADS;
            asm volatile("cp.async.ca.shared.global [%0], [%1], 16;"
                         :: "r"(dh + idx * 16), "l"((const char*)Wfh + idx * 16));
            asm volatile("cp.async.ca.shared.global [%0], [%1], 16;"
                         :: "r"(dl + idx * 16), "l"((const char*)Wfl + idx * 16));
        }
        asm volatile("cp.async.commit_group;");
        asm volatile("cp.async.wait_group 0;" ::: "memory");
    }
    __syncthreads();

    const int wm = w & 7, wn = w >> 3;   // warp grid 8x4, tile 16x32
    const int m0 = wm * 16;

    for (int tile = blockIdx.x; tile < NTILES; tile += GRID) {
        const int node0 = tile * TILE;

        // ---- Gather: warp handles 4 nodes; lane owns channels [4*lane, +4) ----
        {
            F4    acc[4];
            int   eidx[4];
            float sn[4];
#pragma unroll
            for (int i = 0; i < 4; i++) {
                const int gn = node0 + w * 4 + i;
                sn[i] = g_isd[gn];
                int m = -1;
                if (lane < EE) m = edge[(size_t)gn * EE + lane];
                eidx[i] = (m < 0) ? BN : ((gn / NN) * NN + m);
                acc[i].v = *((const float4*)(zin + (size_t)gn * CC) + lane);
            }
#pragma unroll 4
            for (int e = 0; e < EE; e++) {
#pragma unroll
                for (int i = 0; i < 4; i++) {
                    int m = __shfl_sync(0xffffffffu, eidx[i], e);
                    F4 v; v.v = *((const float4*)(zin + (size_t)m * CC) + lane);
                    acc[i].p[0] = add2(acc[i].p[0], v.p[0]);
                    acc[i].p[1] = add2(acc[i].p[1], v.p[1]);
                }
            }
#pragma unroll
            for (int i = 0; i < 4; i++) {
                u64 sd = dup2(sn[i]);
                acc[i].p[0] = mul2(acc[i].p[0], sd);
                acc[i].p[1] = mul2(acc[i].p[1], sd);
                *(float4*)(us + (w * 4 + i) * USTRIDE + lane * 4) = acc[i].v;
            }
            if (t < TILE) isd_s[t] = g_isd[node0 + t];
        }
        __syncthreads();

        // ---- GEMM: warp computes V[m0..m0+16)[32*wn..+32), K=128 ----
        float acc[4][4];
#pragma unroll
        for (int g = 0; g < 4; g++)
#pragma unroll
            for (int j = 0; j < 4; j++) acc[g][j] = 0.0f;

        for (int ks = 0; ks < 16; ks++) {
            const int k0 = ks * 8;
            u32 ah[4], al[4];
            {
                const float* ub = us + (m0 + gid) * USTRIDE + k0 + tid;
                float x0 = ub[0];
                float x1 = ub[8 * USTRIDE];
                float x2 = ub[4];
                float x3 = ub[8 * USTRIDE + 4];
                ah[0] = tf32cvt(x0); al[0] = tf32cvt(x0 - __uint_as_float(ah[0]));
                ah[1] = tf32cvt(x1); al[1] = tf32cvt(x1 - __uint_as_float(ah[1]));
                ah[2] = tf32cvt(x2); al[2] = tf32cvt(x2 - __uint_as_float(ah[2]));
                ah[3] = tf32cvt(x3); al[3] = tf32cvt(x3 - __uint_as_float(ah[3]));
            }
#pragma unroll
            for (int g = 0; g < 4; g++) {
                const int nb = wn * 4 + g;
                float2 bh = Wfh_s[(ks * 16 + nb) * 32 + lane];
                float2 bl = Wfl_s[(ks * 16 + nb) * 32 + lane];
                u32 bh0 = __float_as_uint(bh.x), bh1 = __float_as_uint(bh.y);
                u32 bl0 = __float_as_uint(bl.x), bl1 = __float_as_uint(bl.y);
                mma8(acc[g], ah, bh0, bh1);
                mma8(acc[g], al, bh0, bh1);
                mma8(acc[g], ah, bl0, bl1);
            }
        }

        // ---- Epilogue: ELU (+isd), float2 stores ----
        {
            const int r0 = m0 + gid;
            float s0 = isd_s[r0], s1 = isd_s[r0 + 8];
#pragma unroll
            for (int g = 0; g < 4; g++) {
                const int c = wn * 32 + g * 8 + 2 * tid;
                float2 v0, v1;
                v0.x = elu(acc[g][0]); v0.y = elu(acc[g][1]);
                v1.x = elu(acc[g][2]); v1.y = elu(acc[g][3]);
                if (!LAST) {
                    v0.x *= s0; v0.y *= s0;
                    v1.x *= s1; v1.y *= s1;
                }
                *(float2*)(out + (size_t)(node0 + r0) * CC + c) = v0;
                *(float2*)(out + (size_t)(node0 + r0 + 8) * CC + c) = v1;
            }
        }
        __syncthreads();   // us free for next tile's gather
    }
}

extern "C" void kernel_launch(void* const* d_in, const int* in_sizes, int n_in,
                              void* d_out, int out_size) {
    const float* x    = (const float*)d_in[0];
    const int*   edge = (const int*)d_in[1];
    const float* W0   = (const float*)d_in[2];
    const float* W1   = (const float*)d_in[3];
    const float* W2   = (const float*)d_in[4];
    float* out = (float*)d_out;

    float *bufA = nullptr, *bufB = nullptr;
    float2 *Wfh = nullptr, *Wfl = nullptr;
    cudaGetSymbolAddress((void**)&bufA, g_bufA);
    cudaGetSymbolAddress((void**)&bufB, g_bufB);
    cudaGetSymbolAddress((void**)&Wfh,  g_Wfh);
    cudaGetSymbolAddress((void**)&Wfl,  g_Wfl);

    const int smem_bytes = (2 * 16 * 16 * 32 * 2 + TILE * USTRIDE + TILE) * sizeof(float);
    cudaFuncSetAttribute(layer_kernel<false>,
                         cudaFuncAttributeMaxDynamicSharedMemorySize, smem_bytes);
    cudaFuncSetAttribute(layer_kernel<true>,
                         cudaFuncAttributeMaxDynamicSharedMemorySize, smem_bytes);

    isd_kernel<<<(BN + 255) / 256, 256>>>(edge);

    const int zthreads = BN * (CC / 4) + (CC / 4);
    zprep_kernel<<<(zthreads + 255) / 256, 256>>>(x);

    wfrag_kernel<<<(3 * 16 * 16 * 32 + 255) / 256, 256>>>(W0, W1, W2);

    const int FS = 16 * 16 * 32;   // frags per layer
    layer_kernel<false><<<GRID, THREADS, smem_bytes>>>(bufA, edge, Wfh + 0 * FS, Wfl + 0 * FS, bufB);
    layer_kernel<false><<<GRID, THREADS, smem_bytes>>>(bufB, edge, Wfh + 1 * FS, Wfl + 1 * FS, bufA);
    layer_kernel<true ><<<GRID, THREADS, smem_bytes>>>(bufA, edge, Wfh + 2 * FS, Wfl + 2 * FS, out);
}

// round 12
// speedup vs baseline: 2.1274x; 1.2527x over previous
#include <cuda_runtime.h>
#include <math.h>

#define BB 4
#define NN 20000
#define EE 16
#define CC 128
#define BN (BB*NN)

#define THREADS 1024
#define TILE 64
#define NTILES (BN / TILE)     // 1250
#define GRID 148
#define USTRIDE 132            // us row stride (pad): conflict-free frag LDS

typedef unsigned long long u64;
typedef unsigned int u32;

// Scratch (+1 zero pad row at index BN for -1 edges)
__device__ float g_isd[BN];
__device__ float g_bufA[((size_t)BN + 1) * CC];
__device__ float g_bufB[((size_t)BN + 1) * CC];
// B fragments in mma lane order: [layer][ks(16)][nb(16)][lane(32)] float2 (b0,b1)
__device__ float2 g_Wfh[3 * 16 * 16 * 32];
__device__ float2 g_Wfl[3 * 16 * 16 * 32];

union F4 { float4 v; u64 p[2]; float f[4]; };

__device__ __forceinline__ u64 add2(u64 a, u64 b) {
    u64 d; asm("add.rn.f32x2 %0,%1,%2;" : "=l"(d) : "l"(a), "l"(b)); return d;
}
__device__ __forceinline__ u64 mul2(u64 a, u64 b) {
    u64 d; asm("mul.rn.f32x2 %0,%1,%2;" : "=l"(d) : "l"(a), "l"(b)); return d;
}
__device__ __forceinline__ u64 dup2(float s) {
    u64 d; asm("mov.b64 %0,{%1,%1};" : "=l"(d) : "f"(s)); return d;
}
__device__ __forceinline__ u32 tf32cvt(float f) {
    u32 r; asm("cvt.rna.tf32.f32 %0,%1;" : "=r"(r) : "f"(f)); return r;
}
__device__ __forceinline__ u32 smem_u32(const void* p) {
    u32 a;
    asm("{ .reg .u64 t; cvta.to.shared.u64 t, %1; cvt.u32.u64 %0, t; }" : "=r"(a) : "l"(p));
    return a;
}
__device__ __forceinline__ float elu(float v) { return v > 0.0f ? v : expm1f(v); }

// D(16x8,f32) += A(16x8,tf32,row) * B(8x8,tf32,col)
__device__ __forceinline__ void mma8(float* c, const u32* a, u32 b0, u32 b1) {
    asm("mma.sync.aligned.m16n8k8.row.col.f32.tf32.tf32.f32 "
        "{%0,%1,%2,%3}, {%4,%5,%6,%7}, {%8,%9}, {%0,%1,%2,%3};"
        : "+f"(c[0]), "+f"(c[1]), "+f"(c[2]), "+f"(c[3])
        : "r"(a[0]), "r"(a[1]), "r"(a[2]), "r"(a[3]), "r"(b0), "r"(b1));
}

#define BAR_SYNC(id)   asm volatile("bar.sync %0, %1;"   :: "r"(id), "r"(THREADS) : "memory")
#define BAR_ARRIVE(id) asm volatile("bar.arrive %0, %1;" :: "r"(id), "r"(THREADS) : "memory")
// ids: FULL[b] = 1+b, EMPTY[b] = 3+b

// ---- prep kernels ----
__global__ void isd_kernel(const int* __restrict__ edge) {
    int g = blockIdx.x * blockDim.x + threadIdx.x;
    if (g >= BN) return;
    const int* e = edge + (size_t)g * EE;
    int d = 1;
#pragma unroll
    for (int i = 0; i < EE; i++) d += (e[i] >= 0);
    g_isd[g] = rsqrtf((float)d);
}

__global__ void zprep_kernel(const float* __restrict__ x) {
    int t = blockIdx.x * blockDim.x + threadIdx.x;   // one float4 per thread
    if (t < BN * (CC / 4)) {
        int row = t >> 5;
        float s = g_isd[row];
        F4 v; v.v = *(const float4*)(x + (size_t)t * 4);
        u64 sd = dup2(s);
        v.p[0] = mul2(v.p[0], sd);
        v.p[1] = mul2(v.p[1], sd);
        *(float4*)(g_bufA + (size_t)t * 4) = v.v;
    } else {
        int r = t - BN * (CC / 4);
        if (r < CC / 4) {
            *(float4*)(g_bufA + (size_t)BN * CC + r * 4) = make_float4(0, 0, 0, 0);
            *(float4*)(g_bufB + (size_t)BN * CC + r * 4) = make_float4(0, 0, 0, 0);
        }
    }
}

// Pack W into mma B-fragment order, hi/lo tf32 split.
// B block (ks, nb): k in [8ks,8ks+8), n in [8nb,8nb+8).
// lane: gid=lane>>2, tid=lane&3. b0 = B[k=tid][n=gid], b1 = B[k=tid+4][n=gid].
// B[k][n] = W[n][k]  (V = U @ W^T).
__global__ void wfrag_kernel(const float* __restrict__ W0,
                             const float* __restrict__ W1,
                             const float* __restrict__ W2) {
    int t = blockIdx.x * blockDim.x + threadIdx.x;
    if (t >= 3 * 16 * 16 * 32) return;
    int lane = t & 31;
    int nb   = (t >> 5) & 15;
    int ks   = (t >> 9) & 15;
    int l    = t >> 13;
    int gid = lane >> 2, tid = lane & 3;
    const float* W = (l == 0) ? W0 : (l == 1) ? W1 : W2;
    float v0 = W[(8 * nb + gid) * CC + (8 * ks + tid)];
    float v1 = W[(8 * nb + gid) * CC + (8 * ks + tid + 4)];
    u32 h0 = tf32cvt(v0), h1 = tf32cvt(v1);
    float2 hi, lo;
    hi.x = __uint_as_float(h0);
    hi.y = __uint_as_float(h1);
    lo.x = __uint_as_float(tf32cvt(v0 - hi.x));
    lo.y = __uint_as_float(tf32cvt(v1 - hi.y));
    g_Wfh[t] = hi;
    g_Wfl[t] = lo;
}

// ---- fused layer: producer warps gather -> us[buf]; consumer warps mma+ELU ----
template<bool LAST>
__global__ __launch_bounds__(THREADS, 1)
void layer_kernel(const float* __restrict__ zin,
                  const int*   __restrict__ edge,
                  const float2* __restrict__ Wfh,
                  const float2* __restrict__ Wfl,
                  float*       __restrict__ out)
{
    extern __shared__ float sm[];
    float2* Wfh_s = (float2*)sm;                          // 64 KB
    float2* Wfl_s = Wfh_s + 16 * 16 * 32;                 // 64 KB
    float*  us2   = (float*)(Wfl_s + 16 * 16 * 32);       // [2][64][USTRIDE]
    float*  isd_s = us2 + 2 * TILE * USTRIDE;             // [2][64]

    const int t = threadIdx.x, w = t >> 5, lane = t & 31;
    const int gid = lane >> 2, tid = lane & 3;

    // Stage W fragments once (cp.async). 64 KB per array = 4096 x 16B chunks.
    {
        const u32 dh = smem_u32(Wfh_s), dl = smem_u32(Wfl_s);
#pragma unroll
        for (int i = 0; i < 4096 / THREADS; i++) {
            int idx = t + i * THREADS;
            asm volatile("cp.async.ca.shared.global [%0], [%1], 16;"
                         :: "r"(dh + idx * 16), "l"((const char*)Wfh + idx * 16));
            asm volatile("cp.async.ca.shared.global [%0], [%1], 16;"
                         :: "r"(dl + idx * 16), "l"((const char*)Wfl + idx * 16));
        }
        asm volatile("cp.async.commit_group;");
        asm volatile("cp.async.wait_group 0;" ::: "memory");
    }
    __syncthreads();

    if (w < 16) {
        // ---------------- producer: gather 4 nodes per tile ------------------
        int it = 0;
        for (int tile = blockIdx.x; tile < NTILES; tile += GRID, it++) {
            const int buf = it & 1;
            float* ub = us2 + buf * (TILE * USTRIDE);
            const int node0 = tile * TILE;

            if (it >= 2) BAR_SYNC(3 + buf);              // wait buffer empty

            F4    acc[4];
            int   eidx[4];
            float sn[4];
#pragma unroll
            for (int i = 0; i < 4; i++) {
                const int gn = node0 + w * 4 + i;
                sn[i] = g_isd[gn];
                int m = -1;
                if (lane < EE) m = edge[(size_t)gn * EE + lane];
                eidx[i] = (m < 0) ? BN : ((gn / NN) * NN + m);
                acc[i].v = *((const float4*)(zin + (size_t)gn * CC) + lane);
            }
#pragma unroll 4
            for (int e = 0; e < EE; e++) {
#pragma unroll
                for (int i = 0; i < 4; i++) {
                    int m = __shfl_sync(0xffffffffu, eidx[i], e);
                    F4 v; v.v = *((const float4*)(zin + (size_t)m * CC) + lane);
                    acc[i].p[0] = add2(acc[i].p[0], v.p[0]);
                    acc[i].p[1] = add2(acc[i].p[1], v.p[1]);
                }
            }
#pragma unroll
            for (int i = 0; i < 4; i++) {
                u64 sd = dup2(sn[i]);
                acc[i].p[0] = mul2(acc[i].p[0], sd);
                acc[i].p[1] = mul2(acc[i].p[1], sd);
                *(float4*)(ub + (w * 4 + i) * USTRIDE + lane * 4) = acc[i].v;
            }
            if (lane < 4) isd_s[buf * TILE + w * 4 + lane] = g_isd[node0 + w * 4 + lane];

            BAR_ARRIVE(1 + buf);                         // signal buffer full
        }
    } else {
        // ---------------- consumer: 16x32 mma tile + epilogue ----------------
        const int cw = w - 16, wm = cw & 3, wn = cw >> 2;   // 4x4 warp grid over 64x128
        const int m0 = wm * 16;

        int it = 0;
        for (int tile = blockIdx.x; tile < NTILES; tile += GRID, it++) {
            const int buf = it & 1;
            const float* ub = us2 + buf * (TILE * USTRIDE);
            const int node0 = tile * TILE;

            BAR_SYNC(1 + buf);                           // wait buffer full

            float acc[4][4];
#pragma unroll
            for (int g = 0; g < 4; g++)
#pragma unroll
                for (int j = 0; j < 4; j++) acc[g][j] = 0.0f;

            for (int ks = 0; ks < 16; ks++) {
                const int k0 = ks * 8;
                u32 ah[4], al[4];
                {
                    const float* ua = ub + (m0 + gid) * USTRIDE + k0 + tid;
                    float x0 = ua[0];
                    float x1 = ua[8 * USTRIDE];
                    float x2 = ua[4];
                    float x3 = ua[8 * USTRIDE + 4];
                    ah[0] = tf32cvt(x0); al[0] = tf32cvt(x0 - __uint_as_float(ah[0]));
                    ah[1] = tf32cvt(x1); al[1] = tf32cvt(x1 - __uint_as_float(ah[1]));
                    ah[2] = tf32cvt(x2); al[2] = tf32cvt(x2 - __uint_as_float(ah[2]));
                    ah[3] = tf32cvt(x3); al[3] = tf32cvt(x3 - __uint_as_float(ah[3]));
                }
#pragma unroll
                for (int g = 0; g < 4; g++) {
                    const int nb = wn * 4 + g;
                    float2 bh = Wfh_s[(ks * 16 + nb) * 32 + lane];
                    float2 bl = Wfl_s[(ks * 16 + nb) * 32 + lane];
                    u32 bh0 = __float_as_uint(bh.x), bh1 = __float_as_uint(bh.y);
                    u32 bl0 = __float_as_uint(bl.x), bl1 = __float_as_uint(bl.y);
                    mma8(acc[g], ah, bh0, bh1);
                    mma8(acc[g], al, bh0, bh1);
                    mma8(acc[g], ah, bl0, bl1);
                }
            }

            const int r0 = m0 + gid;
            float s0 = isd_s[buf * TILE + r0];
            float s1 = isd_s[buf * TILE + r0 + 8];

            BAR_ARRIVE(3 + buf);                         // buffer free for producer

            // epilogue from registers (no buffer dependence)
#pragma unroll
            for (int g = 0; g < 4; g++) {
                const int c = wn * 32 + g * 8 + 2 * tid;
                float2 v0, v1;
                v0.x = elu(acc[g][0]); v0.y = elu(acc[g][1]);
                v1.x = elu(acc[g][2]); v1.y = elu(acc[g][3]);
                if (!LAST) {
                    v0.x *= s0; v0.y *= s0;
                    v1.x *= s1; v1.y *= s1;
                }
                *(float2*)(out + (size_t)(node0 + r0) * CC + c) = v0;
                *(float2*)(out + (size_t)(node0 + r0 + 8) * CC + c) = v1;
            }
        }
    }
}

extern "C" void kernel_launch(void* const* d_in, const int* in_sizes, int n_in,
                              void* d_out, int out_size) {
    const float* x    = (const float*)d_in[0];
    const int*   edge = (const int*)d_in[1];
    const float* W0   = (const float*)d_in[2];
    const float* W1   = (const float*)d_in[3];
    const float* W2   = (const float*)d_in[4];
    float* out = (float*)d_out;

    float *bufA = nullptr, *bufB = nullptr;
    float2 *Wfh = nullptr, *Wfl = nullptr;
    cudaGetSymbolAddress((void**)&bufA, g_bufA);
    cudaGetSymbolAddress((void**)&bufB, g_bufB);
    cudaGetSymbolAddress((void**)&Wfh,  g_Wfh);
    cudaGetSymbolAddress((void**)&Wfl,  g_Wfl);

    const int smem_bytes =
        (2 * 16 * 16 * 32 * 2 + 2 * TILE * USTRIDE + 2 * TILE) * sizeof(float);  // ~199 KB
    cudaFuncSetAttribute(layer_kernel<false>,
                         cudaFuncAttributeMaxDynamicSharedMemorySize, smem_bytes);
    cudaFuncSetAttribute(layer_kernel<true>,
                         cudaFuncAttributeMaxDynamicSharedMemorySize, smem_bytes);

    isd_kernel<<<(BN + 255) / 256, 256>>>(edge);

    const int zthreads = BN * (CC / 4) + (CC / 4);
    zprep_kernel<<<(zthreads + 255) / 256, 256>>>(x);

    wfrag_kernel<<<(3 * 16 * 16 * 32 + 255) / 256, 256>>>(W0, W1, W2);

    const int FS = 16 * 16 * 32;   // frags per layer
    layer_kernel<false><<<GRID, THREADS, smem_bytes>>>(bufA, edge, Wfh + 0 * FS, Wfl + 0 * FS, bufB);
    layer_kernel<false><<<GRID, THREADS, smem_bytes>>>(bufB, edge, Wfh + 1 * FS, Wfl + 1 * FS, bufA);
    layer_kernel<true ><<<GRID, THREADS, smem_bytes>>>(bufA, edge, Wfh + 2 * FS, Wfl + 2 * FS, out);
}